// round 10
// baseline (speedup 1.0000x reference)
#include <cuda_runtime.h>
#include <cuda_bf16.h>
#include <cstdint>

#define BB 8
#define NN 2048
#define HH 256

// ---------------- device scratch ----------------
__device__ __align__(16) __nv_bfloat16 g_xh[BB*NN*HH];
__device__ __align__(16) __nv_bfloat16 g_xl[BB*NN*HH];
__device__ __align__(16) __nv_bfloat16 g_yh[BB*NN*HH];
__device__ __align__(16) __nv_bfloat16 g_yl[BB*NN*HH];
__device__ __align__(16) __nv_bfloat16 g_Wqh[HH*HH];
__device__ __align__(16) __nv_bfloat16 g_Wql[HH*HH];
__device__ __align__(16) __nv_bfloat16 g_Wkh[HH*HH];
__device__ __align__(16) __nv_bfloat16 g_Wkl[HH*HH];
__device__ __align__(16) __nv_bfloat16 g_Ah[HH*HH];   // (Wq Wk^T)^T / 16, bf16 hi/lo
__device__ __align__(16) __nv_bfloat16 g_Al[HH*HH];
__device__ __align__(16) float g_w[BB*NN];
__device__ __align__(16) float g_t[BB*NN];
__device__ __align__(16) float g_u[HH];
__device__ __align__(16) float g_p[HH];
__device__ float g_c;

// ---------------- helpers ----------------
__device__ __forceinline__ uint32_t smem_u32(const void* p) {
    return (uint32_t)__cvta_generic_to_shared(p);
}
__device__ __forceinline__ void cp16(uint32_t dst, const void* src) {
    asm volatile("cp.async.cg.shared.global [%0], [%1], 16;" :: "r"(dst), "l"(src));
}
__device__ __forceinline__ void cp_commit() { asm volatile("cp.async.commit_group;"); }
template <int N> __device__ __forceinline__ void cp_wait() {
    asm volatile("cp.async.wait_group %0;" :: "n"(N) : "memory");
}
__device__ __forceinline__ void ldsm4(uint32_t* d, uint32_t addr) {
    asm volatile("ldmatrix.sync.aligned.m8n8.x4.shared.b16 {%0,%1,%2,%3}, [%4];"
        : "=r"(d[0]), "=r"(d[1]), "=r"(d[2]), "=r"(d[3]) : "r"(addr));
}
__device__ __forceinline__ void mma16816(float* c, const uint32_t* a,
                                         uint32_t b0, uint32_t b1) {
    asm volatile("mma.sync.aligned.m16n8k16.row.col.f32.bf16.bf16.f32 "
        "{%0,%1,%2,%3}, {%4,%5,%6,%7}, {%8,%9}, {%0,%1,%2,%3};"
        : "+f"(c[0]), "+f"(c[1]), "+f"(c[2]), "+f"(c[3])
        : "r"(a[0]), "r"(a[1]), "r"(a[2]), "r"(a[3]), "r"(b0), "r"(b1));
}
#define SW128(o) ((o) ^ (((o) >> 3) & 0x70))
__device__ __forceinline__ uint32_t pack_bf(__nv_bfloat16 a, __nv_bfloat16 b) {
    return (uint32_t)__bfloat16_as_ushort(a) | ((uint32_t)__bfloat16_as_ushort(b) << 16);
}
__device__ __forceinline__ void split2(float v, __nv_bfloat16& h, __nv_bfloat16& l) {
    h = __float2bfloat16(v);
    l = __float2bfloat16(v - __bfloat162float(h));
}

// Stage a 32-row x 256-dim bf16 hi/lo tile (SW128, 64-dim blocks). 256 threads.
__device__ __forceinline__ void stage32(uint32_t dst, const __nv_bfloat16* ph,
                                        const __nv_bfloat16* pl, int tid) {
    #pragma unroll
    for (int i = 0; i < 4; i++) {
        int idx = tid + i * 256, r = idx >> 5, d = (idx & 31) * 8;
        uint32_t off = (uint32_t)(d >> 6) * 4096u + SW128((uint32_t)(r * 128 + (d & 63) * 2));
        cp16(dst + off, ph + (size_t)r * HH + d);
        cp16(dst + 16384u + off, pl + (size_t)r * HH + d);
    }
}
// 64-row x 256-dim hi/lo tile, 512 threads. hi at dst (32KB), lo at dst+32768.
__device__ __forceinline__ void stage64_512(uint32_t dst, const __nv_bfloat16* ph,
                                            const __nv_bfloat16* pl, int tid) {
    #pragma unroll
    for (int i = 0; i < 4; i++) {
        int idx = tid + i * 512, r = idx >> 5, d = (idx & 31) * 8;
        uint32_t off = (uint32_t)(d >> 6) * 8192u + SW128((uint32_t)(r * 128 + (d & 63) * 2));
        cp16(dst + off, ph + (size_t)r * HH + d);
        cp16(dst + 32768u + off, pl + (size_t)r * HH + d);
    }
}
// 128-row A tile, 256 threads: hi at hbase, lo at lbase (64-dim blocks stride 16384).
__device__ __forceinline__ void stageA2(uint32_t hbase, uint32_t lbase,
                                        const __nv_bfloat16* ph, const __nv_bfloat16* pl,
                                        int tid) {
    #pragma unroll
    for (int i = 0; i < 16; i++) {
        int idx = tid + i * 256, r = idx >> 5, d = (idx & 31) * 8;
        uint32_t off = (uint32_t)(d >> 6) * 16384u + SW128((uint32_t)(r * 128 + (d & 63) * 2));
        cp16(hbase + off, ph + (size_t)r * HH + d);
        cp16(lbase + off, pl + (size_t)r * HH + d);
    }
}
// 128-row A tile, 512 threads.
__device__ __forceinline__ void stageA2_512(uint32_t hbase, uint32_t lbase,
                                            const __nv_bfloat16* ph, const __nv_bfloat16* pl,
                                            int tid) {
    #pragma unroll
    for (int i = 0; i < 8; i++) {
        int idx = tid + i * 512, r = idx >> 5, d = (idx & 31) * 8;
        uint32_t off = (uint32_t)(d >> 6) * 16384u + SW128((uint32_t)(r * 128 + (d & 63) * 2));
        cp16(hbase + off, ph + (size_t)r * HH + d);
        cp16(lbase + off, pl + (size_t)r * HH + d);
    }
}
// Preload this warp's A-hi fragments: 16 kk-steps x 4 regs (base: hi region).
__device__ __forceinline__ void preloadA(uint32_t hbase, uint32_t sq, uint32_t ahr[16][4]) {
    #pragma unroll
    for (int kk = 0; kk < 16; kk++) {
        uint32_t cx = (uint32_t)(kk & 3) * 32u;
        uint32_t bq = (uint32_t)(kk >> 2) * 16384u;
        ldsm4(ahr[kk], hbase + bq + (sq ^ cx));
    }
}

// 128x32x256 score block (gemm path, R4-proven). A-hi regs, A-lo at albase, B at kbuf.
__device__ __forceinline__ void score32(uint32_t albase, uint32_t kbuf,
                                        const uint32_t ahr[16][4], uint32_t sq,
                                        uint32_t sk0, uint32_t sk1, float a4[4][4]) {
    #pragma unroll
    for (int kk = 0; kk < 16; kk++) {
        const uint32_t cx = (uint32_t)(kk & 3) * 32u;
        const uint32_t bq = (uint32_t)(kk >> 2) * 16384u;
        const uint32_t bk = (uint32_t)(kk >> 2) * 4096u;
        uint32_t al[4], b0h[4], b1h[4], b0l[4], b1l[4];
        ldsm4(al, albase + bq + (sq ^ cx));
        ldsm4(b0h, kbuf + bk + (sk0 ^ cx));
        ldsm4(b1h, kbuf + bk + (sk1 ^ cx));
        ldsm4(b0l, kbuf + 16384u + bk + (sk0 ^ cx));
        ldsm4(b1l, kbuf + 16384u + bk + (sk1 ^ cx));
        const uint32_t* ah = ahr[kk];
        mma16816(a4[0], ah, b0h[0], b0h[1]);
        mma16816(a4[1], ah, b0h[2], b0h[3]);
        mma16816(a4[2], ah, b1h[0], b1h[1]);
        mma16816(a4[3], ah, b1h[2], b1h[3]);
        mma16816(a4[0], ah, b0l[0], b0l[1]);
        mma16816(a4[1], ah, b0l[2], b0l[3]);
        mma16816(a4[2], ah, b1l[0], b1l[1]);
        mma16816(a4[3], ah, b1l[2], b1l[3]);
        mma16816(a4[0], al, b0h[0], b0h[1]);
        mma16816(a4[1], al, b0h[2], b0h[3]);
        mma16816(a4[2], al, b1h[0], b1h[1]);
        mma16816(a4[3], al, b1h[2], b1h[3]);
    }
}

// 128x32x256 score block for key-split attn: this warp's 32-key slice of a
// 64-key tile. A-hi regs, A-lo at albase (stride 16384), B at kbuf (64-row
// layout: hi blocks stride 8192, lo at +32768). sk0 already includes the
// key-half offset (+kh*4096).
__device__ __forceinline__ void score32ks(uint32_t albase, uint32_t kbuf,
                                          const uint32_t ahr[16][4], uint32_t sq,
                                          uint32_t sk0, float a4[4][4]) {
    #pragma unroll
    for (int kk = 0; kk < 16; kk++) {
        const uint32_t cx = (uint32_t)(kk & 3) * 32u;
        const uint32_t bq = (uint32_t)(kk >> 2) * 16384u;
        const uint32_t bk = (uint32_t)(kk >> 2) * 8192u;
        uint32_t al[4], bh[2][4], bl[2][4];
        ldsm4(al, albase + bq + (sq ^ cx));
        #pragma unroll
        for (int t = 0; t < 2; t++) {
            uint32_t sk = (sk0 + (uint32_t)t * 2048u) ^ cx;
            ldsm4(bh[t], kbuf + bk + sk);
            ldsm4(bl[t], kbuf + 32768u + bk + sk);
        }
        const uint32_t* ah = ahr[kk];
        #pragma unroll
        for (int t = 0; t < 2; t++) {
            mma16816(a4[2 * t], ah, bh[t][0], bh[t][1]);
            mma16816(a4[2 * t + 1], ah, bh[t][2], bh[t][3]);
        }
        #pragma unroll
        for (int t = 0; t < 2; t++) {
            mma16816(a4[2 * t], ah, bl[t][0], bl[t][1]);
            mma16816(a4[2 * t + 1], ah, bl[t][2], bl[t][3]);
        }
        #pragma unroll
        for (int t = 0; t < 2; t++) {
            mma16816(a4[2 * t], al, bh[t][0], bh[t][1]);
            mma16816(a4[2 * t + 1], al, bh[t][2], bh[t][3]);
        }
    }
}

// ---------------- kernel 0: u = Wv@Ww, p = (Wk@bq)/16, c = bv.Ww ----------------
__global__ void prep_kernel(const float* __restrict__ Wv, const float* __restrict__ Ww,
                            const float* __restrict__ bv, const float* __restrict__ Wk,
                            const float* __restrict__ bq) {
    int warp = threadIdx.x >> 5, lane = threadIdx.x & 31;
    for (int row = warp; row < HH; row += 8) {
        float su = 0.f, sp = 0.f;
        #pragma unroll
        for (int m = 0; m < 8; m++) {
            su += Wv[row * HH + m * 32 + lane] * Ww[m * 32 + lane];
            sp += Wk[row * HH + m * 32 + lane] * bq[m * 32 + lane];
        }
        for (int o = 16; o; o >>= 1) {
            su += __shfl_down_sync(0xffffffffu, su, o);
            sp += __shfl_down_sync(0xffffffffu, sp, o);
        }
        if (!lane) { g_u[row] = su; g_p[row] = sp * 0.0625f; }
    }
    if (threadIdx.x == 0) {
        float c = 0.f;
        for (int j = 0; j < HH; j++) c += bv[j] * Ww[j];
        g_c = c;
    }
}

// ---------------- kernel 1: plain bf16 hi/lo splits of Wq, Wk ----------------
__global__ void prep_w2_kernel(const float* __restrict__ Wq, const float* __restrict__ Wk) {
    int j = blockIdx.y, d = threadIdx.x;
    const float* W = blockIdx.x ? Wk : Wq;
    __nv_bfloat16* oh = blockIdx.x ? g_Wkh : g_Wqh;
    __nv_bfloat16* ol = blockIdx.x ? g_Wkl : g_Wql;
    __nv_bfloat16 hi, lo;
    split2(W[j * HH + d], hi, lo);
    oh[j * HH + d] = hi;
    ol[j * HH + d] = lo;
}

// ---------------- kernel 2: split x + w = x.u + c, t = x.p ----------------
__global__ void xw_kernel(const float* __restrict__ x) {
    int warp = threadIdx.x >> 5, lane = threadIdx.x & 31;
    int row = blockIdx.x * 8 + warp;
    const float* xr = x + (size_t)row * HH + lane * 8;
    const float* up = g_u + lane * 8;
    const float* pp = g_p + lane * 8;
    uint32_t hi[4], lo[4];
    float s = 0.f, s2 = 0.f;
    #pragma unroll
    for (int g = 0; g < 2; g++) {
        float4 v = *(const float4*)(xr + g * 4);
        __nv_bfloat16 h0, l0, h1, l1, h2, l2, h3, l3;
        split2(v.x, h0, l0); split2(v.y, h1, l1);
        split2(v.z, h2, l2); split2(v.w, h3, l3);
        hi[g * 2] = pack_bf(h0, h1); hi[g * 2 + 1] = pack_bf(h2, h3);
        lo[g * 2] = pack_bf(l0, l1); lo[g * 2 + 1] = pack_bf(l2, l3);
        s  += v.x * up[g * 4] + v.y * up[g * 4 + 1] + v.z * up[g * 4 + 2] + v.w * up[g * 4 + 3];
        s2 += v.x * pp[g * 4] + v.y * pp[g * 4 + 1] + v.z * pp[g * 4 + 2] + v.w * pp[g * 4 + 3];
    }
    *(uint4*)(g_xh + (size_t)row * HH + lane * 8) = *(uint4*)hi;
    *(uint4*)(g_xl + (size_t)row * HH + lane * 8) = *(uint4*)lo;
    for (int o = 16; o; o >>= 1) {
        s += __shfl_down_sync(0xffffffffu, s, o);
        s2 += __shfl_down_sync(0xffffffffu, s2, o);
    }
    if (!lane) { g_w[row] = s + g_c; g_t[row] = s2; }
}

// ---------------- kernel 3: unified split-output GEMM (R6-proven) ----------------
// smem: A 131072 | B bufs 65536 => 196608
#define GM_SMEM 196608
__global__ __launch_bounds__(256, 1) void gemm_mma(int mode) {
    extern __shared__ __align__(1024) char sm[];
    const uint32_t smb = smem_u32(sm);
    const int tid = threadIdx.x, warp = tid >> 5, lane = tid & 31;
    const int m0 = blockIdx.x * 128;
    const int jiters = mode ? 8 : 1;
    const int col_base = mode ? 0 : blockIdx.y * 32;
    const float scale = mode ? 1.0f : 0.0625f;
    const __nv_bfloat16* Aph = (mode ? g_xh : g_Wkh) + (size_t)m0 * HH;
    const __nv_bfloat16* Apl = (mode ? g_xl : g_Wkl) + (size_t)m0 * HH;
    const __nv_bfloat16* Bph = (mode ? g_Ah : g_Wqh) + (size_t)col_base * HH;
    const __nv_bfloat16* Bpl = (mode ? g_Al : g_Wql) + (size_t)col_base * HH;
    __nv_bfloat16* Oh = mode ? g_yh : g_Ah;
    __nv_bfloat16* Ol = mode ? g_yl : g_Al;

    stageA2(smb, smb + 65536u, Aph, Apl, tid);
    cp_commit();
    stage32(smb + 131072u, Bph, Bpl, tid); cp_commit();
    if (jiters > 1) stage32(smb + 131072u + 32768u, Bph + 32 * HH, Bpl + 32 * HH, tid);
    cp_commit();

    uint32_t qrowb = (uint32_t)((warp * 16 + (lane & 15)) * 128 + (lane >> 4) * 16);
    uint32_t sq = qrowb ^ ((qrowb >> 3) & 0x70);
    uint32_t kr0 = (uint32_t)((((lane & 7) + ((lane >> 4) << 3))) * 128 + ((lane & 8) << 1));
    uint32_t sk0 = kr0 ^ ((kr0 >> 3) & 0x70);
    uint32_t sk1 = sk0 + 2048u;
    const int r0 = m0 + warp * 16 + (lane >> 2);

    cp_wait<2>(); __syncthreads();
    uint32_t ahr[16][4];
    preloadA(smb, sq, ahr);

    for (int j = 0; j < jiters; j++) {
        cp_wait<1>(); __syncthreads();
        float acc[4][4];
        #pragma unroll
        for (int a = 0; a < 4; a++)
            #pragma unroll
            for (int b2 = 0; b2 < 4; b2++) acc[a][b2] = 0.f;
        score32(smb + 65536u, smb + 131072u + (uint32_t)(j & 1) * 32768u, ahr, sq, sk0, sk1, acc);
        __syncthreads();
        if (j + 2 < jiters) {
            stage32(smb + 131072u + (uint32_t)(j & 1) * 32768u,
                    Bph + (size_t)(j + 2) * 32 * HH, Bpl + (size_t)(j + 2) * 32 * HH, tid);
            cp_commit();
        }
        #pragma unroll
        for (int nt = 0; nt < 4; nt++) {
            int col = col_base + j * 32 + nt * 8 + (lane & 3) * 2;
            float v00 = acc[nt][0] * scale, v01 = acc[nt][1] * scale;
            float v10 = acc[nt][2] * scale, v11 = acc[nt][3] * scale;
            __nv_bfloat16 h0, l0, h1, l1;
            split2(v00, h0, l0); split2(v01, h1, l1);
            *(uint32_t*)(Oh + (size_t)r0 * HH + col) = pack_bf(h0, h1);
            *(uint32_t*)(Ol + (size_t)r0 * HH + col) = pack_bf(l0, l1);
            split2(v10, h0, l0); split2(v11, h1, l1);
            *(uint32_t*)(Oh + (size_t)(r0 + 8) * HH + col) = pack_bf(h0, h1);
            *(uint32_t*)(Ol + (size_t)(r0 + 8) * HH + col) = pack_bf(l0, l1);
        }
    }
}

// ---------------- kernel 4: fused attention (512 thr, key-split warps) ----------------
// smem: [0,64K) Y-lo | [64K,128K) buf0 (hi 32K + lo 32K) | [128K,192K) buf1
//       (Y-hi staged into buf1 region at startup, consumed into regs)
//       ring @196608: 4 x (w 256B + t 256B) = 2048 | scratch @198656: 2x128x8B.
#define AT_SMEM 200704
#define RING_OFF 196608u
#define SCR_OFF 198656u
__global__ __launch_bounds__(512, 1) void attn_mma4(const float* __restrict__ bw,
                                                    float* __restrict__ out) {
    extern __shared__ __align__(1024) char sm[];
    const uint32_t smb = smem_u32(sm);
    const int tid = threadIdx.x, warp = tid >> 5, lane = tid & 31;
    const int wq = warp & 7;      // q-row group (16 rows each)
    const int kh = warp >> 3;     // key half of the 64-key tile
    const int b = blockIdx.y, n0 = blockIdx.x * 128;

    const __nv_bfloat16* xh = g_xh + (size_t)b * NN * HH;
    const __nv_bfloat16* xl = g_xl + (size_t)b * NN * HH;
    const float* wsrc = g_w + b * NN;
    const float* tsrc = g_t + b * NN;

    // stage Y: hi -> buf1 region (131072), lo -> [0,64K)
    stageA2_512(smb + 131072u, smb, g_yh + (size_t)(b * NN + n0) * HH,
                g_yl + (size_t)(b * NN + n0) * HH, tid);
    cp_commit();

    uint32_t qrowb = (uint32_t)((wq * 16 + (lane & 15)) * 128 + (lane >> 4) * 16);
    uint32_t sq = qrowb ^ ((qrowb >> 3) & 0x70);
    uint32_t kr0 = (uint32_t)((((lane & 7) + ((lane >> 4) << 3))) * 128 + ((lane & 8) << 1));
    uint32_t sk0 = (kr0 ^ ((kr0 >> 3) & 0x70)) + (uint32_t)kh * 4096u;

    cp_wait<0>(); __syncthreads();
    uint32_t ahr[16][4];
    preloadA(smb + 131072u, sq, ahr);
    __syncthreads();   // all preloads done before buf1 is overwritten

    // stage B tiles 0 (buf0) and 1 (buf1) + (w,t) ring entries
    #pragma unroll
    for (int j0 = 0; j0 < 2; j0++) {
        stage64_512(smb + 65536u + (uint32_t)j0 * 65536u, xh + (size_t)j0 * 64 * HH,
                    xl + (size_t)j0 * 64 * HH, tid);
        if (tid < 16) cp16(smb + RING_OFF + (uint32_t)j0 * 512u + tid * 16u,
                           wsrc + j0 * 64 + tid * 4);
        else if (tid < 32) cp16(smb + RING_OFF + (uint32_t)j0 * 512u + 256u + (tid - 16) * 16u,
                                tsrc + j0 * 64 + (tid - 16) * 4);
        cp_commit();
    }

    float num0 = 0.f, den0 = 0.f, num1 = 0.f, den1 = 0.f;
    for (int j = 0; j < 32; j++) {
        cp_wait<1>(); __syncthreads();
        float acc[4][4];
        #pragma unroll
        for (int a = 0; a < 4; a++)
            #pragma unroll
            for (int b2 = 0; b2 < 4; b2++) acc[a][b2] = 0.f;
        score32ks(smb, smb + 65536u + (uint32_t)(j & 1) * 65536u, ahr, sq, sk0, acc);
        __syncthreads();
        if (j + 2 < 32) {
            stage64_512(smb + 65536u + (uint32_t)(j & 1) * 65536u,
                        xh + (size_t)(j + 2) * 64 * HH, xl + (size_t)(j + 2) * 64 * HH, tid);
            if (tid < 16) cp16(smb + RING_OFF + (uint32_t)((j + 2) & 3) * 512u + tid * 16u,
                               wsrc + (j + 2) * 64 + tid * 4);
            else if (tid < 32) cp16(smb + RING_OFF + (uint32_t)((j + 2) & 3) * 512u + 256u +
                                        (tid - 16) * 16u,
                                    tsrc + (j + 2) * 64 + (tid - 16) * 4);
            cp_commit();
        }
        const float* wsp = (const float*)(sm + RING_OFF + (j & 3) * 512) + kh * 32;
        const float* tsp = wsp + 64;
        #pragma unroll
        for (int nt = 0; nt < 2; nt++) {
            // acc tiles 2t..2t+1 cover keys t*16 + {0..15} of this warp's 32-key slice
            float2 wv0 = *(const float2*)(wsp + nt * 16 + (lane & 3) * 2);
            float2 tv0 = *(const float2*)(tsp + nt * 16 + (lane & 3) * 2);
            float2 wv1 = *(const float2*)(wsp + nt * 16 + 8 + (lane & 3) * 2);
            float2 tv1 = *(const float2*)(tsp + nt * 16 + 8 + (lane & 3) * 2);
            float e;
            e = __expf(acc[2 * nt][0] + tv0.x); den0 += e; num0 += e * wv0.x;
            e = __expf(acc[2 * nt][1] + tv0.y); den0 += e; num0 += e * wv0.y;
            e = __expf(acc[2 * nt][2] + tv0.x); den1 += e; num1 += e * wv0.x;
            e = __expf(acc[2 * nt][3] + tv0.y); den1 += e; num1 += e * wv0.y;
            e = __expf(acc[2 * nt + 1][0] + tv1.x); den0 += e; num0 += e * wv1.x;
            e = __expf(acc[2 * nt + 1][1] + tv1.y); den0 += e; num0 += e * wv1.y;
            e = __expf(acc[2 * nt + 1][2] + tv1.x); den1 += e; num1 += e * wv1.x;
            e = __expf(acc[2 * nt + 1][3] + tv1.y); den1 += e; num1 += e * wv1.y;
        }
    }
    // lane-quad reduce (lanes sharing a q-row)
    #pragma unroll
    for (int o = 1; o <= 2; o <<= 1) {
        num0 += __shfl_xor_sync(0xffffffffu, num0, o);
        den0 += __shfl_xor_sync(0xffffffffu, den0, o);
        num1 += __shfl_xor_sync(0xffffffffu, num1, o);
        den1 += __shfl_xor_sync(0xffffffffu, den1, o);
    }
    // cross-half combine via smem scratch
    if (!(lane & 3)) {
        int r = wq * 16 + (lane >> 2);
        *(float2*)(sm + SCR_OFF + (uint32_t)kh * 1024u + (uint32_t)r * 8u) =
            make_float2(num0, den0);
        *(float2*)(sm + SCR_OFF + (uint32_t)kh * 1024u + (uint32_t)(r + 8) * 8u) =
            make_float2(num1, den1);
    }
    __syncthreads();
    if (tid < 128) {
        float2 a = *(const float2*)(sm + SCR_OFF + (uint32_t)tid * 8u);
        float2 b2 = *(const float2*)(sm + SCR_OFF + 1024u + (uint32_t)tid * 8u);
        out[b * NN + n0 + tid] = (a.x + b2.x) / (a.y + b2.y) + __ldg(bw);
    }
}

// ---------------- launch ----------------
extern "C" void kernel_launch(void* const* d_in, const int* in_sizes, int n_in,
                              void* d_out, int out_size) {
    const float* x  = (const float*)d_in[0];
    const float* Wq = (const float*)d_in[1];
    const float* bq = (const float*)d_in[2];
    const float* Wk = (const float*)d_in[3];
    const float* bk = (const float*)d_in[4];
    const float* Wv = (const float*)d_in[5];
    const float* bv = (const float*)d_in[6];
    const float* Ww = (const float*)d_in[7];
    const float* bw = (const float*)d_in[8];
    float* out = (float*)d_out;
    (void)bk;

    cudaFuncSetAttribute(gemm_mma, cudaFuncAttributeMaxDynamicSharedMemorySize, GM_SMEM);
    cudaFuncSetAttribute(attn_mma4, cudaFuncAttributeMaxDynamicSharedMemorySize, AT_SMEM);

    prep_kernel<<<1, 256>>>(Wv, Ww, bv, Wk, bq);
    prep_w2_kernel<<<dim3(2, 256), 256>>>(Wq, Wk);
    gemm_mma<<<dim3(2, 8), 256, GM_SMEM>>>(0);       // Amat = (WqWk^T)^T / 16
    xw_kernel<<<BB * NN / 8, 256>>>(x);              // split x, w, t
    gemm_mma<<<dim3(128, 1), 256, GM_SMEM>>>(1);     // y = x * Amat
    attn_mma4<<<dim3(16, 8), 512, AT_SMEM>>>(bw, out);
}

// round 11
// speedup vs baseline: 1.6577x; 1.6577x over previous
#include <cuda_runtime.h>
#include <cuda_bf16.h>
#include <cuda_fp16.h>
#include <cstdint>

#define BB 8
#define NN 2048
#define HH 256

// ---------------- device scratch ----------------
__device__ __align__(16) __nv_bfloat16 g_xh[BB*NN*HH];
__device__ __align__(16) __nv_bfloat16 g_xl[BB*NN*HH];
__device__ __align__(16) __half       g_x16[BB*NN*HH];
__device__ __align__(16) __half       g_y16[BB*NN*HH];
__device__ __align__(16) __nv_bfloat16 g_Wqh[HH*HH];
__device__ __align__(16) __nv_bfloat16 g_Wql[HH*HH];
__device__ __align__(16) __nv_bfloat16 g_Wkh[HH*HH];
__device__ __align__(16) __nv_bfloat16 g_Wkl[HH*HH];
__device__ __align__(16) __nv_bfloat16 g_Ah[HH*HH];   // (Wq Wk^T)^T / 16, bf16 hi/lo
__device__ __align__(16) __nv_bfloat16 g_Al[HH*HH];
__device__ __align__(16) float g_w[BB*NN];
__device__ __align__(16) float g_t[BB*NN];
__device__ __align__(16) float g_u[HH];
__device__ __align__(16) float g_p[HH];
__device__ float g_c;

// ---------------- helpers ----------------
__device__ __forceinline__ uint32_t smem_u32(const void* p) {
    return (uint32_t)__cvta_generic_to_shared(p);
}
__device__ __forceinline__ void cp16(uint32_t dst, const void* src) {
    asm volatile("cp.async.cg.shared.global [%0], [%1], 16;" :: "r"(dst), "l"(src));
}
__device__ __forceinline__ void cp_commit() { asm volatile("cp.async.commit_group;"); }
template <int N> __device__ __forceinline__ void cp_wait() {
    asm volatile("cp.async.wait_group %0;" :: "n"(N) : "memory");
}
__device__ __forceinline__ void ldsm4(uint32_t* d, uint32_t addr) {
    asm volatile("ldmatrix.sync.aligned.m8n8.x4.shared.b16 {%0,%1,%2,%3}, [%4];"
        : "=r"(d[0]), "=r"(d[1]), "=r"(d[2]), "=r"(d[3]) : "r"(addr));
}
__device__ __forceinline__ void mma16816(float* c, const uint32_t* a,
                                         uint32_t b0, uint32_t b1) {
    asm volatile("mma.sync.aligned.m16n8k16.row.col.f32.bf16.bf16.f32 "
        "{%0,%1,%2,%3}, {%4,%5,%6,%7}, {%8,%9}, {%0,%1,%2,%3};"
        : "+f"(c[0]), "+f"(c[1]), "+f"(c[2]), "+f"(c[3])
        : "r"(a[0]), "r"(a[1]), "r"(a[2]), "r"(a[3]), "r"(b0), "r"(b1));
}
__device__ __forceinline__ void mma16816h(float* c, const uint32_t* a,
                                          uint32_t b0, uint32_t b1) {
    asm volatile("mma.sync.aligned.m16n8k16.row.col.f32.f16.f16.f32 "
        "{%0,%1,%2,%3}, {%4,%5,%6,%7}, {%8,%9}, {%0,%1,%2,%3};"
        : "+f"(c[0]), "+f"(c[1]), "+f"(c[2]), "+f"(c[3])
        : "r"(a[0]), "r"(a[1]), "r"(a[2]), "r"(a[3]), "r"(b0), "r"(b1));
}
#define SW128(o) ((o) ^ (((o) >> 3) & 0x70))
__device__ __forceinline__ uint32_t pack_bf(__nv_bfloat16 a, __nv_bfloat16 b) {
    return (uint32_t)__bfloat16_as_ushort(a) | ((uint32_t)__bfloat16_as_ushort(b) << 16);
}
__device__ __forceinline__ uint32_t pack_h(float a, float b) {
    __half2 h = __floats2half2_rn(a, b);
    return *(uint32_t*)&h;
}
__device__ __forceinline__ void split2(float v, __nv_bfloat16& h, __nv_bfloat16& l) {
    h = __float2bfloat16(v);
    l = __float2bfloat16(v - __bfloat162float(h));
}

// Stage a 32-row x 256-dim bf16 hi/lo tile (SW128, 64-dim blocks). 256 threads.
__device__ __forceinline__ void stage32(uint32_t dst, const __nv_bfloat16* ph,
                                        const __nv_bfloat16* pl, int tid) {
    #pragma unroll
    for (int i = 0; i < 4; i++) {
        int idx = tid + i * 256, r = idx >> 5, d = (idx & 31) * 8;
        uint32_t off = (uint32_t)(d >> 6) * 4096u + SW128((uint32_t)(r * 128 + (d & 63) * 2));
        cp16(dst + off, ph + (size_t)r * HH + d);
        cp16(dst + 16384u + off, pl + (size_t)r * HH + d);
    }
}
// 128-row A tile, 256 threads: hi at hbase, lo at lbase (64-dim blocks stride 16384).
__device__ __forceinline__ void stageA2(uint32_t hbase, uint32_t lbase,
                                        const __nv_bfloat16* ph, const __nv_bfloat16* pl,
                                        int tid) {
    #pragma unroll
    for (int i = 0; i < 16; i++) {
        int idx = tid + i * 256, r = idx >> 5, d = (idx & 31) * 8;
        uint32_t off = (uint32_t)(d >> 6) * 16384u + SW128((uint32_t)(r * 128 + (d & 63) * 2));
        cp16(hbase + off, ph + (size_t)r * HH + d);
        cp16(lbase + off, pl + (size_t)r * HH + d);
    }
}
// 128-row x 256-dim fp16 tile at dst (64 KB, 64-dim blocks stride 16384).
__device__ __forceinline__ void stageY16(uint32_t dst, const __half* p, int tid) {
    #pragma unroll
    for (int i = 0; i < 16; i++) {
        int idx = tid + i * 256, r = idx >> 5, d = (idx & 31) * 8;
        uint32_t off = (uint32_t)(d >> 6) * 16384u + SW128((uint32_t)(r * 128 + (d & 63) * 2));
        cp16(dst + off, p + (size_t)r * HH + d);
    }
}
// 64-row x 256-dim fp16 tile at dst (32 KB, 64-dim blocks stride 8192).
__device__ __forceinline__ void stage64h(uint32_t dst, const __half* p, int tid) {
    #pragma unroll
    for (int i = 0; i < 8; i++) {
        int idx = tid + i * 256, r = idx >> 5, d = (idx & 31) * 8;
        uint32_t off = (uint32_t)(d >> 6) * 8192u + SW128((uint32_t)(r * 128 + (d & 63) * 2));
        cp16(dst + off, p + (size_t)r * HH + d);
    }
}
// Preload this warp's A fragments: 16 kk-steps x 4 regs (blocks stride 16384).
__device__ __forceinline__ void preloadA(uint32_t hbase, uint32_t sq, uint32_t ahr[16][4]) {
    #pragma unroll
    for (int kk = 0; kk < 16; kk++) {
        uint32_t cx = (uint32_t)(kk & 3) * 32u;
        uint32_t bq = (uint32_t)(kk >> 2) * 16384u;
        ldsm4(ahr[kk], hbase + bq + (sq ^ cx));
    }
}

// 128x32x256 score block (bf16 3-pass, gemm path, R6-proven).
__device__ __forceinline__ void score32(uint32_t albase, uint32_t kbuf,
                                        const uint32_t ahr[16][4], uint32_t sq,
                                        uint32_t sk0, uint32_t sk1, float a4[4][4]) {
    #pragma unroll
    for (int kk = 0; kk < 16; kk++) {
        const uint32_t cx = (uint32_t)(kk & 3) * 32u;
        const uint32_t bq = (uint32_t)(kk >> 2) * 16384u;
        const uint32_t bk = (uint32_t)(kk >> 2) * 4096u;
        uint32_t al[4], b0h[4], b1h[4], b0l[4], b1l[4];
        ldsm4(al, albase + bq + (sq ^ cx));
        ldsm4(b0h, kbuf + bk + (sk0 ^ cx));
        ldsm4(b1h, kbuf + bk + (sk1 ^ cx));
        ldsm4(b0l, kbuf + 16384u + bk + (sk0 ^ cx));
        ldsm4(b1l, kbuf + 16384u + bk + (sk1 ^ cx));
        const uint32_t* ah = ahr[kk];
        mma16816(a4[0], ah, b0h[0], b0h[1]);
        mma16816(a4[1], ah, b0h[2], b0h[3]);
        mma16816(a4[2], ah, b1h[0], b1h[1]);
        mma16816(a4[3], ah, b1h[2], b1h[3]);
        mma16816(a4[0], ah, b0l[0], b0l[1]);
        mma16816(a4[1], ah, b0l[2], b0l[3]);
        mma16816(a4[2], ah, b1l[0], b1l[1]);
        mma16816(a4[3], ah, b1l[2], b1l[3]);
        mma16816(a4[0], al, b0h[0], b0h[1]);
        mma16816(a4[1], al, b0h[2], b0h[3]);
        mma16816(a4[2], al, b1h[0], b1h[1]);
        mma16816(a4[3], al, b1h[2], b1h[3]);
    }
}

// 128x64x256 fp16 single-pass score block (attn). A in regs, B at kbuf
// (64-row fp16 layout: 64-dim blocks stride 8192).
__device__ __forceinline__ void score64h(uint32_t kbuf, const uint32_t ahr[16][4],
                                         uint32_t sk0, float a4[8][4]) {
    #pragma unroll
    for (int kk = 0; kk < 16; kk++) {
        const uint32_t cx = (uint32_t)(kk & 3) * 32u;
        const uint32_t bk = (uint32_t)(kk >> 2) * 8192u;
        uint32_t bh[4][4];
        #pragma unroll
        for (int t = 0; t < 4; t++)
            ldsm4(bh[t], kbuf + bk + ((sk0 + (uint32_t)t * 2048u) ^ cx));
        const uint32_t* ah = ahr[kk];
        #pragma unroll
        for (int t = 0; t < 4; t++) {
            mma16816h(a4[2 * t], ah, bh[t][0], bh[t][1]);
            mma16816h(a4[2 * t + 1], ah, bh[t][2], bh[t][3]);
        }
    }
}

// ---------------- kernel 0: u = Wv@Ww, p = (Wk@bq)/16, c = bv.Ww ----------------
__global__ void prep_kernel(const float* __restrict__ Wv, const float* __restrict__ Ww,
                            const float* __restrict__ bv, const float* __restrict__ Wk,
                            const float* __restrict__ bq) {
    int warp = threadIdx.x >> 5, lane = threadIdx.x & 31;
    for (int row = warp; row < HH; row += 8) {
        float su = 0.f, sp = 0.f;
        #pragma unroll
        for (int m = 0; m < 8; m++) {
            su += Wv[row * HH + m * 32 + lane] * Ww[m * 32 + lane];
            sp += Wk[row * HH + m * 32 + lane] * bq[m * 32 + lane];
        }
        for (int o = 16; o; o >>= 1) {
            su += __shfl_down_sync(0xffffffffu, su, o);
            sp += __shfl_down_sync(0xffffffffu, sp, o);
        }
        if (!lane) { g_u[row] = su; g_p[row] = sp * 0.0625f; }
    }
    if (threadIdx.x == 0) {
        float c = 0.f;
        for (int j = 0; j < HH; j++) c += bv[j] * Ww[j];
        g_c = c;
    }
}

// ---------------- kernel 1: plain bf16 hi/lo splits of Wq, Wk ----------------
__global__ void prep_w2_kernel(const float* __restrict__ Wq, const float* __restrict__ Wk) {
    int j = blockIdx.y, d = threadIdx.x;
    const float* W = blockIdx.x ? Wk : Wq;
    __nv_bfloat16* oh = blockIdx.x ? g_Wkh : g_Wqh;
    __nv_bfloat16* ol = blockIdx.x ? g_Wkl : g_Wql;
    __nv_bfloat16 hi, lo;
    split2(W[j * HH + d], hi, lo);
    oh[j * HH + d] = hi;
    ol[j * HH + d] = lo;
}

// ---------------- kernel 2: split x (bf16 hi/lo + fp16) + w, t scalars ----------------
__global__ void xw_kernel(const float* __restrict__ x) {
    int warp = threadIdx.x >> 5, lane = threadIdx.x & 31;
    int row = blockIdx.x * 8 + warp;
    const float* xr = x + (size_t)row * HH + lane * 8;
    const float* up = g_u + lane * 8;
    const float* pp = g_p + lane * 8;
    uint32_t hi[4], lo[4], h16[4];
    float s = 0.f, s2 = 0.f;
    #pragma unroll
    for (int g = 0; g < 2; g++) {
        float4 v = *(const float4*)(xr + g * 4);
        __nv_bfloat16 h0, l0, h1, l1, h2, l2, h3, l3;
        split2(v.x, h0, l0); split2(v.y, h1, l1);
        split2(v.z, h2, l2); split2(v.w, h3, l3);
        hi[g * 2] = pack_bf(h0, h1); hi[g * 2 + 1] = pack_bf(h2, h3);
        lo[g * 2] = pack_bf(l0, l1); lo[g * 2 + 1] = pack_bf(l2, l3);
        h16[g * 2] = pack_h(v.x, v.y); h16[g * 2 + 1] = pack_h(v.z, v.w);
        s  += v.x * up[g * 4] + v.y * up[g * 4 + 1] + v.z * up[g * 4 + 2] + v.w * up[g * 4 + 3];
        s2 += v.x * pp[g * 4] + v.y * pp[g * 4 + 1] + v.z * pp[g * 4 + 2] + v.w * pp[g * 4 + 3];
    }
    *(uint4*)(g_xh + (size_t)row * HH + lane * 8) = *(uint4*)hi;
    *(uint4*)(g_xl + (size_t)row * HH + lane * 8) = *(uint4*)lo;
    *(uint4*)(g_x16 + (size_t)row * HH + lane * 8) = *(uint4*)h16;
    for (int o = 16; o; o >>= 1) {
        s += __shfl_down_sync(0xffffffffu, s, o);
        s2 += __shfl_down_sync(0xffffffffu, s2, o);
    }
    if (!lane) { g_w[row] = s + g_c; g_t[row] = s2; }
}

// ---------------- kernel 3: unified split-output GEMM ----------------
// mode 0: Amat = (WqWk^T)^T/16 -> g_Ah/g_Al (bf16 split).  mode 1: y = x*Amat -> g_y16 (fp16).
// smem: A 131072 | B bufs 65536 => 196608
#define GM_SMEM 196608
__global__ __launch_bounds__(256, 1) void gemm_mma(int mode) {
    extern __shared__ __align__(1024) char sm[];
    const uint32_t smb = smem_u32(sm);
    const int tid = threadIdx.x, warp = tid >> 5, lane = tid & 31;
    const int m0 = blockIdx.x * 128;
    const int jiters = mode ? 8 : 1;
    const int col_base = mode ? 0 : blockIdx.y * 32;
    const float scale = mode ? 1.0f : 0.0625f;
    const __nv_bfloat16* Aph = (mode ? g_xh : g_Wkh) + (size_t)m0 * HH;
    const __nv_bfloat16* Apl = (mode ? g_xl : g_Wkl) + (size_t)m0 * HH;
    const __nv_bfloat16* Bph = (mode ? g_Ah : g_Wqh) + (size_t)col_base * HH;
    const __nv_bfloat16* Bpl = (mode ? g_Al : g_Wql) + (size_t)col_base * HH;

    stageA2(smb, smb + 65536u, Aph, Apl, tid);
    cp_commit();
    stage32(smb + 131072u, Bph, Bpl, tid); cp_commit();
    if (jiters > 1) stage32(smb + 131072u + 32768u, Bph + 32 * HH, Bpl + 32 * HH, tid);
    cp_commit();

    uint32_t qrowb = (uint32_t)((warp * 16 + (lane & 15)) * 128 + (lane >> 4) * 16);
    uint32_t sq = qrowb ^ ((qrowb >> 3) & 0x70);
    uint32_t kr0 = (uint32_t)((((lane & 7) + ((lane >> 4) << 3))) * 128 + ((lane & 8) << 1));
    uint32_t sk0 = kr0 ^ ((kr0 >> 3) & 0x70);
    uint32_t sk1 = sk0 + 2048u;
    const int r0 = m0 + warp * 16 + (lane >> 2);

    cp_wait<2>(); __syncthreads();
    uint32_t ahr[16][4];
    preloadA(smb, sq, ahr);

    for (int j = 0; j < jiters; j++) {
        cp_wait<1>(); __syncthreads();
        float acc[4][4];
        #pragma unroll
        for (int a = 0; a < 4; a++)
            #pragma unroll
            for (int b2 = 0; b2 < 4; b2++) acc[a][b2] = 0.f;
        score32(smb + 65536u, smb + 131072u + (uint32_t)(j & 1) * 32768u, ahr, sq, sk0, sk1, acc);
        __syncthreads();
        if (j + 2 < jiters) {
            stage32(smb + 131072u + (uint32_t)(j & 1) * 32768u,
                    Bph + (size_t)(j + 2) * 32 * HH, Bpl + (size_t)(j + 2) * 32 * HH, tid);
            cp_commit();
        }
        #pragma unroll
        for (int nt = 0; nt < 4; nt++) {
            int col = col_base + j * 32 + nt * 8 + (lane & 3) * 2;
            float v00 = acc[nt][0] * scale, v01 = acc[nt][1] * scale;
            float v10 = acc[nt][2] * scale, v11 = acc[nt][3] * scale;
            if (mode) {
                *(uint32_t*)(g_y16 + (size_t)r0 * HH + col) = pack_h(v00, v01);
                *(uint32_t*)(g_y16 + (size_t)(r0 + 8) * HH + col) = pack_h(v10, v11);
            } else {
                __nv_bfloat16 h0, l0, h1, l1;
                split2(v00, h0, l0); split2(v01, h1, l1);
                *(uint32_t*)(g_Ah + (size_t)r0 * HH + col) = pack_bf(h0, h1);
                *(uint32_t*)(g_Al + (size_t)r0 * HH + col) = pack_bf(l0, l1);
                split2(v10, h0, l0); split2(v11, h1, l1);
                *(uint32_t*)(g_Ah + (size_t)(r0 + 8) * HH + col) = pack_bf(h0, h1);
                *(uint32_t*)(g_Al + (size_t)(r0 + 8) * HH + col) = pack_bf(l0, l1);
            }
        }
    }
}

// ---------------- kernel 4: fused attention (fp16 single-pass) ----------------
// smem: [0,64K) Y16 staging -> reused as two 32K B buffers | ring @65536: 4x512B.
#define ATF_SMEM (65536 + 2048)
#define RINGF 65536u
__global__ __launch_bounds__(256, 1) void attn_f16(const float* __restrict__ bw,
                                                   float* __restrict__ out) {
    extern __shared__ __align__(1024) char sm[];
    const uint32_t smb = smem_u32(sm);
    const int tid = threadIdx.x, warp = tid >> 5, lane = tid & 31;
    const int b = blockIdx.y, n0 = blockIdx.x * 128;

    const __half* xp = g_x16 + (size_t)b * NN * HH;
    const float* wsrc = g_w + b * NN;
    const float* tsrc = g_t + b * NN;

    // stage Y16 (128 x 256 fp16) into [0,64K), consume into registers
    stageY16(smb, g_y16 + (size_t)(b * NN + n0) * HH, tid);
    cp_commit();

    uint32_t qrowb = (uint32_t)((warp * 16 + (lane & 15)) * 128 + (lane >> 4) * 16);
    uint32_t sq = qrowb ^ ((qrowb >> 3) & 0x70);
    uint32_t kr0 = (uint32_t)((((lane & 7) + ((lane >> 4) << 3))) * 128 + ((lane & 8) << 1));
    uint32_t sk0 = kr0 ^ ((kr0 >> 3) & 0x70);

    cp_wait<0>(); __syncthreads();
    uint32_t ahr[16][4];
    preloadA(smb, sq, ahr);
    __syncthreads();   // preloads done before the Y area is reused as B buffers

    // stage B tiles 0 (buf [0,32K)) and 1 (buf [32K,64K)) + (w,t) ring
    #pragma unroll
    for (int j0 = 0; j0 < 2; j0++) {
        stage64h(smb + (uint32_t)j0 * 32768u, xp + (size_t)j0 * 64 * HH, tid);
        if (tid < 16) cp16(smb + RINGF + (uint32_t)j0 * 512u + tid * 16u,
                           wsrc + j0 * 64 + tid * 4);
        else if (tid < 32) cp16(smb + RINGF + (uint32_t)j0 * 512u + 256u + (tid - 16) * 16u,
                                tsrc + j0 * 64 + (tid - 16) * 4);
        cp_commit();
    }

    float num0 = 0.f, den0 = 0.f, num1 = 0.f, den1 = 0.f;
    for (int j = 0; j < 32; j++) {
        cp_wait<1>(); __syncthreads();
        float acc[8][4];
        #pragma unroll
        for (int a = 0; a < 8; a++)
            #pragma unroll
            for (int b2 = 0; b2 < 4; b2++) acc[a][b2] = 0.f;
        score64h(smb + (uint32_t)(j & 1) * 32768u, ahr, sk0, acc);
        __syncthreads();
        if (j + 2 < 32) {
            stage64h(smb + (uint32_t)(j & 1) * 32768u, xp + (size_t)(j + 2) * 64 * HH, tid);
            if (tid < 16) cp16(smb + RINGF + (uint32_t)((j + 2) & 3) * 512u + tid * 16u,
                               wsrc + (j + 2) * 64 + tid * 4);
            else if (tid < 32) cp16(smb + RINGF + (uint32_t)((j + 2) & 3) * 512u + 256u +
                                        (tid - 16) * 16u,
                                    tsrc + (j + 2) * 64 + (tid - 16) * 4);
            cp_commit();
        }
        const float* wsp = (const float*)(sm + RINGF + (j & 3) * 512);
        const float* tsp = wsp + 64;
        #pragma unroll
        for (int nt = 0; nt < 8; nt++) {
            float2 wv = *(const float2*)(wsp + nt * 8 + (lane & 3) * 2);
            float2 tv = *(const float2*)(tsp + nt * 8 + (lane & 3) * 2);
            float e;
            e = __expf(acc[nt][0] + tv.x); den0 += e; num0 += e * wv.x;
            e = __expf(acc[nt][1] + tv.y); den0 += e; num0 += e * wv.y;
            e = __expf(acc[nt][2] + tv.x); den1 += e; num1 += e * wv.x;
            e = __expf(acc[nt][3] + tv.y); den1 += e; num1 += e * wv.y;
        }
    }
    #pragma unroll
    for (int o = 1; o <= 2; o <<= 1) {
        num0 += __shfl_xor_sync(0xffffffffu, num0, o);
        den0 += __shfl_xor_sync(0xffffffffu, den0, o);
        num1 += __shfl_xor_sync(0xffffffffu, num1, o);
        den1 += __shfl_xor_sync(0xffffffffu, den1, o);
    }
    if (!(lane & 3)) {
        int r = n0 + warp * 16 + (lane >> 2);
        float bwv = __ldg(bw);
        out[b * NN + r] = num0 / den0 + bwv;
        out[b * NN + r + 8] = num1 / den1 + bwv;
    }
}

// ---------------- launch ----------------
extern "C" void kernel_launch(void* const* d_in, const int* in_sizes, int n_in,
                              void* d_out, int out_size) {
    const float* x  = (const float*)d_in[0];
    const float* Wq = (const float*)d_in[1];
    const float* bq = (const float*)d_in[2];
    const float* Wk = (const float*)d_in[3];
    const float* bk = (const float*)d_in[4];
    const float* Wv = (const float*)d_in[5];
    const float* bv = (const float*)d_in[6];
    const float* Ww = (const float*)d_in[7];
    const float* bw = (const float*)d_in[8];
    float* out = (float*)d_out;
    (void)bk;

    cudaFuncSetAttribute(gemm_mma, cudaFuncAttributeMaxDynamicSharedMemorySize, GM_SMEM);
    cudaFuncSetAttribute(attn_f16, cudaFuncAttributeMaxDynamicSharedMemorySize, ATF_SMEM);

    prep_kernel<<<1, 256>>>(Wv, Ww, bv, Wk, bq);
    prep_w2_kernel<<<dim3(2, 256), 256>>>(Wq, Wk);
    gemm_mma<<<dim3(2, 8), 256, GM_SMEM>>>(0);       // Amat = (WqWk^T)^T / 16
    xw_kernel<<<BB * NN / 8, 256>>>(x);              // split x, w, t
    gemm_mma<<<dim3(128, 1), 256, GM_SMEM>>>(1);     // y = x * Amat -> fp16
    attn_f16<<<dim3(16, 8), 256, ATF_SMEM>>>(bw, out);
}

// round 13
// speedup vs baseline: 1.8038x; 1.0881x over previous
#include <cuda_runtime.h>
#include <cuda_bf16.h>
#include <cuda_fp16.h>
#include <cstdint>

#define BB 8
#define NN 2048
#define HH 256

// ---------------- device scratch ----------------
__device__ __align__(16) __half       g_x16[BB*NN*HH];
__device__ __align__(16) __half       g_y16[BB*NN*HH];
__device__ __align__(16) __half       g_A16[HH*HH];   // Amat^T [col][dim], fp16
__device__ __align__(16) __nv_bfloat16 g_Wqh[HH*HH];
__device__ __align__(16) __nv_bfloat16 g_Wql[HH*HH];
__device__ __align__(16) __nv_bfloat16 g_Wkh[HH*HH];
__device__ __align__(16) __nv_bfloat16 g_Wkl[HH*HH];
__device__ __align__(16) float g_w[BB*NN];
__device__ __align__(16) float g_t[BB*NN];
__device__ __align__(16) float g_u[HH];
__device__ __align__(16) float g_p[HH];
__device__ float g_c;

// ---------------- helpers ----------------
__device__ __forceinline__ uint32_t smem_u32(const void* p) {
    return (uint32_t)__cvta_generic_to_shared(p);
}
__device__ __forceinline__ void cp16(uint32_t dst, const void* src) {
    asm volatile("cp.async.cg.shared.global [%0], [%1], 16;" :: "r"(dst), "l"(src));
}
__device__ __forceinline__ void cp_commit() { asm volatile("cp.async.commit_group;"); }
template <int N> __device__ __forceinline__ void cp_wait() {
    asm volatile("cp.async.wait_group %0;" :: "n"(N) : "memory");
}
__device__ __forceinline__ void ldsm4(uint32_t* d, uint32_t addr) {
    asm volatile("ldmatrix.sync.aligned.m8n8.x4.shared.b16 {%0,%1,%2,%3}, [%4];"
        : "=r"(d[0]), "=r"(d[1]), "=r"(d[2]), "=r"(d[3]) : "r"(addr));
}
__device__ __forceinline__ void mma16816(float* c, const uint32_t* a,
                                         uint32_t b0, uint32_t b1) {
    asm volatile("mma.sync.aligned.m16n8k16.row.col.f32.bf16.bf16.f32 "
        "{%0,%1,%2,%3}, {%4,%5,%6,%7}, {%8,%9}, {%0,%1,%2,%3};"
        : "+f"(c[0]), "+f"(c[1]), "+f"(c[2]), "+f"(c[3])
        : "r"(a[0]), "r"(a[1]), "r"(a[2]), "r"(a[3]), "r"(b0), "r"(b1));
}
__device__ __forceinline__ void mma16816h(float* c, const uint32_t* a,
                                          uint32_t b0, uint32_t b1) {
    asm volatile("mma.sync.aligned.m16n8k16.row.col.f32.f16.f16.f32 "
        "{%0,%1,%2,%3}, {%4,%5,%6,%7}, {%8,%9}, {%0,%1,%2,%3};"
        : "+f"(c[0]), "+f"(c[1]), "+f"(c[2]), "+f"(c[3])
        : "r"(a[0]), "r"(a[1]), "r"(a[2]), "r"(a[3]), "r"(b0), "r"(b1));
}
#define SW128(o) ((o) ^ (((o) >> 3) & 0x70))
__device__ __forceinline__ uint32_t pack_h(float a, float b) {
    __half2 h = __floats2half2_rn(a, b);
    return *(uint32_t*)&h;
}
__device__ __forceinline__ void split2(float v, __nv_bfloat16& h, __nv_bfloat16& l) {
    h = __float2bfloat16(v);
    l = __float2bfloat16(v - __bfloat162float(h));
}

// Stage a 32-row x 256-dim bf16 hi/lo tile (SW128, 64-dim blocks). 256 threads.
__device__ __forceinline__ void stage32(uint32_t dst, const __nv_bfloat16* ph,
                                        const __nv_bfloat16* pl, int tid) {
    #pragma unroll
    for (int i = 0; i < 4; i++) {
        int idx = tid + i * 256, r = idx >> 5, d = (idx & 31) * 8;
        uint32_t off = (uint32_t)(d >> 6) * 4096u + SW128((uint32_t)(r * 128 + (d & 63) * 2));
        cp16(dst + off, ph + (size_t)r * HH + d);
        cp16(dst + 16384u + off, pl + (size_t)r * HH + d);
    }
}
// 128-row bf16 hi/lo A tile, 256 threads (64-dim blocks stride 16384).
__device__ __forceinline__ void stageA2(uint32_t hbase, uint32_t lbase,
                                        const __nv_bfloat16* ph, const __nv_bfloat16* pl,
                                        int tid) {
    #pragma unroll
    for (int i = 0; i < 16; i++) {
        int idx = tid + i * 256, r = idx >> 5, d = (idx & 31) * 8;
        uint32_t off = (uint32_t)(d >> 6) * 16384u + SW128((uint32_t)(r * 128 + (d & 63) * 2));
        cp16(hbase + off, ph + (size_t)r * HH + d);
        cp16(lbase + off, pl + (size_t)r * HH + d);
    }
}
// 128-row x 256-dim fp16 tile at dst (64 KB, 64-dim blocks stride 16384).
__device__ __forceinline__ void stageY16(uint32_t dst, const __half* p, int tid) {
    #pragma unroll
    for (int i = 0; i < 16; i++) {
        int idx = tid + i * 256, r = idx >> 5, d = (idx & 31) * 8;
        uint32_t off = (uint32_t)(d >> 6) * 16384u + SW128((uint32_t)(r * 128 + (d & 63) * 2));
        cp16(dst + off, p + (size_t)r * HH + d);
    }
}
// 64-row x 256-dim fp16 tile at dst (32 KB, 64-dim blocks stride 8192).
__device__ __forceinline__ void stage64h(uint32_t dst, const __half* p, int tid) {
    #pragma unroll
    for (int i = 0; i < 8; i++) {
        int idx = tid + i * 256, r = idx >> 5, d = (idx & 31) * 8;
        uint32_t off = (uint32_t)(d >> 6) * 8192u + SW128((uint32_t)(r * 128 + (d & 63) * 2));
        cp16(dst + off, p + (size_t)r * HH + d);
    }
}
// Preload this warp's A fragments: 16 kk-steps x 4 regs (blocks stride 16384).
__device__ __forceinline__ void preloadA(uint32_t hbase, uint32_t sq, uint32_t ahr[16][4]) {
    #pragma unroll
    for (int kk = 0; kk < 16; kk++) {
        uint32_t cx = (uint32_t)(kk & 3) * 32u;
        uint32_t bq = (uint32_t)(kk >> 2) * 16384u;
        ldsm4(ahr[kk], hbase + bq + (sq ^ cx));
    }
}

// 128x32x256 bf16 3-pass score block (Amat path, R6-proven).
__device__ __forceinline__ void score32(uint32_t albase, uint32_t kbuf,
                                        const uint32_t ahr[16][4], uint32_t sq,
                                        uint32_t sk0, uint32_t sk1, float a4[4][4]) {
    #pragma unroll
    for (int kk = 0; kk < 16; kk++) {
        const uint32_t cx = (uint32_t)(kk & 3) * 32u;
        const uint32_t bq = (uint32_t)(kk >> 2) * 16384u;
        const uint32_t bk = (uint32_t)(kk >> 2) * 4096u;
        uint32_t al[4], b0h[4], b1h[4], b0l[4], b1l[4];
        ldsm4(al, albase + bq + (sq ^ cx));
        ldsm4(b0h, kbuf + bk + (sk0 ^ cx));
        ldsm4(b1h, kbuf + bk + (sk1 ^ cx));
        ldsm4(b0l, kbuf + 16384u + bk + (sk0 ^ cx));
        ldsm4(b1l, kbuf + 16384u + bk + (sk1 ^ cx));
        const uint32_t* ah = ahr[kk];
        mma16816(a4[0], ah, b0h[0], b0h[1]);
        mma16816(a4[1], ah, b0h[2], b0h[3]);
        mma16816(a4[2], ah, b1h[0], b1h[1]);
        mma16816(a4[3], ah, b1h[2], b1h[3]);
        mma16816(a4[0], ah, b0l[0], b0l[1]);
        mma16816(a4[1], ah, b0l[2], b0l[3]);
        mma16816(a4[2], ah, b1l[0], b1l[1]);
        mma16816(a4[3], ah, b1l[2], b1l[3]);
        mma16816(a4[0], al, b0h[0], b0h[1]);
        mma16816(a4[1], al, b0h[2], b0h[3]);
        mma16816(a4[2], al, b1h[0], b1h[1]);
        mma16816(a4[3], al, b1h[2], b1h[3]);
    }
}

// 128x64x256 fp16 single-pass score block (R11-proven). A in regs, B at kbuf
// (64-row fp16 layout: 64-dim blocks stride 8192).
__device__ __forceinline__ void score64h(uint32_t kbuf, const uint32_t ahr[16][4],
                                         uint32_t sk0, float a4[8][4]) {
    #pragma unroll
    for (int kk = 0; kk < 16; kk++) {
        const uint32_t cx = (uint32_t)(kk & 3) * 32u;
        const uint32_t bk = (uint32_t)(kk >> 2) * 8192u;
        uint32_t bh[4][4];
        #pragma unroll
        for (int t = 0; t < 4; t++)
            ldsm4(bh[t], kbuf + bk + ((sk0 + (uint32_t)t * 2048u) ^ cx));
        const uint32_t* ah = ahr[kk];
        #pragma unroll
        for (int t = 0; t < 4; t++) {
            mma16816h(a4[2 * t], ah, bh[t][0], bh[t][1]);
            mma16816h(a4[2 * t + 1], ah, bh[t][2], bh[t][3]);
        }
    }
}

// ---------------- kernel 0: u = Wv@Ww, p = (Wk@bq)/16, c = bv.Ww ----------------
__global__ void prep_kernel(const float* __restrict__ Wv, const float* __restrict__ Ww,
                            const float* __restrict__ bv, const float* __restrict__ Wk,
                            const float* __restrict__ bq) {
    int warp = threadIdx.x >> 5, lane = threadIdx.x & 31;
    for (int row = warp; row < HH; row += 8) {
        float su = 0.f, sp = 0.f;
        #pragma unroll
        for (int m = 0; m < 8; m++) {
            su += Wv[row * HH + m * 32 + lane] * Ww[m * 32 + lane];
            sp += Wk[row * HH + m * 32 + lane] * bq[m * 32 + lane];
        }
        for (int o = 16; o; o >>= 1) {
            su += __shfl_down_sync(0xffffffffu, su, o);
            sp += __shfl_down_sync(0xffffffffu, sp, o);
        }
        if (!lane) { g_u[row] = su; g_p[row] = sp * 0.0625f; }
    }
    if (threadIdx.x == 0) {
        float c = 0.f;
        for (int j = 0; j < HH; j++) c += bv[j] * Ww[j];
        g_c = c;
    }
}

// ---------------- kernel 1: plain bf16 hi/lo splits of Wq, Wk ----------------
__global__ void prep_w2_kernel(const float* __restrict__ Wq, const float* __restrict__ Wk) {
    int j = blockIdx.y, d = threadIdx.x;
    const float* W = blockIdx.x ? Wk : Wq;
    __nv_bfloat16* oh = blockIdx.x ? g_Wkh : g_Wqh;
    __nv_bfloat16* ol = blockIdx.x ? g_Wkl : g_Wql;
    __nv_bfloat16 hi, lo;
    split2(W[j * HH + d], hi, lo);
    oh[j * HH + d] = hi;
    ol[j * HH + d] = lo;
}

// ---------------- kernel 2: x -> fp16 + w = x.u + c, t = x.p ----------------
__global__ void xw_kernel(const float* __restrict__ x) {
    int warp = threadIdx.x >> 5, lane = threadIdx.x & 31;
    int row = blockIdx.x * 8 + warp;
    const float* xr = x + (size_t)row * HH + lane * 8;
    const float* up = g_u + lane * 8;
    const float* pp = g_p + lane * 8;
    uint32_t h16[4];
    float s = 0.f, s2 = 0.f;
    #pragma unroll
    for (int g = 0; g < 2; g++) {
        float4 v = *(const float4*)(xr + g * 4);
        h16[g * 2] = pack_h(v.x, v.y); h16[g * 2 + 1] = pack_h(v.z, v.w);
        s  += v.x * up[g * 4] + v.y * up[g * 4 + 1] + v.z * up[g * 4 + 2] + v.w * up[g * 4 + 3];
        s2 += v.x * pp[g * 4] + v.y * pp[g * 4 + 1] + v.z * pp[g * 4 + 2] + v.w * pp[g * 4 + 3];
    }
    *(uint4*)(g_x16 + (size_t)row * HH + lane * 8) = *(uint4*)h16;
    for (int o = 16; o; o >>= 1) {
        s += __shfl_down_sync(0xffffffffu, s, o);
        s2 += __shfl_down_sync(0xffffffffu, s2, o);
    }
    if (!lane) { g_w[row] = s + g_c; g_t[row] = s2; }
}

// ---------------- kernel 3: Amat = (WqWk^T)^T/16 -> fp16 (3-pass bf16 compute) ----------------
// grid (2, 8): 128 Wk-rows x 32 Wq-cols per CTA. smem: A 128K + B 32K.
#define AM_SMEM 163840
__global__ __launch_bounds__(256, 1) void amat_mma() {
    extern __shared__ __align__(1024) char sm[];
    const uint32_t smb = smem_u32(sm);
    const int tid = threadIdx.x, warp = tid >> 5, lane = tid & 31;
    const int m0 = blockIdx.x * 128;
    const int cb = blockIdx.y * 32;

    stageA2(smb, smb + 65536u, g_Wkh + (size_t)m0 * HH, g_Wkl + (size_t)m0 * HH, tid);
    cp_commit();
    stage32(smb + 131072u, g_Wqh + (size_t)cb * HH, g_Wql + (size_t)cb * HH, tid);
    cp_commit();

    uint32_t qrowb = (uint32_t)((warp * 16 + (lane & 15)) * 128 + (lane >> 4) * 16);
    uint32_t sq = qrowb ^ ((qrowb >> 3) & 0x70);
    uint32_t kr0 = (uint32_t)((((lane & 7) + ((lane >> 4) << 3))) * 128 + ((lane & 8) << 1));
    uint32_t sk0 = kr0 ^ ((kr0 >> 3) & 0x70);
    uint32_t sk1 = sk0 + 2048u;

    cp_wait<0>(); __syncthreads();
    uint32_t ahr[16][4];
    preloadA(smb, sq, ahr);

    float acc[4][4];
    #pragma unroll
    for (int a = 0; a < 4; a++)
        #pragma unroll
        for (int b2 = 0; b2 < 4; b2++) acc[a][b2] = 0.f;
    score32(smb + 65536u, smb + 131072u, ahr, sq, sk0, sk1, acc);

    const int r0 = m0 + warp * 16 + (lane >> 2);
    #pragma unroll
    for (int nt = 0; nt < 4; nt++) {
        int col = cb + nt * 8 + (lane & 3) * 2;
        *(uint32_t*)(g_A16 + (size_t)r0 * HH + col) =
            pack_h(acc[nt][0] * 0.0625f, acc[nt][1] * 0.0625f);
        *(uint32_t*)(g_A16 + (size_t)(r0 + 8) * HH + col) =
            pack_h(acc[nt][2] * 0.0625f, acc[nt][3] * 0.0625f);
    }
}

// ---------------- kernel 4: y = x * Amat (fp16 single-pass) ----------------
// grid 128: 128 x-rows per CTA, all 256 output cols (4 j-iters of 64 cols).
// smem: [0,64K) x16 staging -> reused as two 32K B buffers.
#define Y16_SMEM 65536
__global__ __launch_bounds__(256, 1) void y16_mma() {
    extern __shared__ __align__(1024) char sm[];
    const uint32_t smb = smem_u32(sm);
    const int tid = threadIdx.x, warp = tid >> 5, lane = tid & 31;
    const int m0 = blockIdx.x * 128;

    stageY16(smb, g_x16 + (size_t)m0 * HH, tid);
    cp_commit();

    uint32_t qrowb = (uint32_t)((warp * 16 + (lane & 15)) * 128 + (lane >> 4) * 16);
    uint32_t sq = qrowb ^ ((qrowb >> 3) & 0x70);
    uint32_t kr0 = (uint32_t)((((lane & 7) + ((lane >> 4) << 3))) * 128 + ((lane & 8) << 1));
    uint32_t sk0 = kr0 ^ ((kr0 >> 3) & 0x70);

    cp_wait<0>(); __syncthreads();
    uint32_t ahr[16][4];
    preloadA(smb, sq, ahr);
    __syncthreads();   // preloads done before x area becomes B buffers

    #pragma unroll
    for (int j0 = 0; j0 < 2; j0++) {
        stage64h(smb + (uint32_t)j0 * 32768u, g_A16 + (size_t)j0 * 64 * HH, tid);
        cp_commit();
    }

    const int r0 = m0 + warp * 16 + (lane >> 2);
    for (int j = 0; j < 4; j++) {
        if (j < 3) { cp_wait<1>(); } else { cp_wait<0>(); }
        __syncthreads();
        float acc[8][4];
        #pragma unroll
        for (int a = 0; a < 8; a++)
            #pragma unroll
            for (int b2 = 0; b2 < 4; b2++) acc[a][b2] = 0.f;
        score64h(smb + (uint32_t)(j & 1) * 32768u, ahr, sk0, acc);
        __syncthreads();
        if (j + 2 < 4) {
            stage64h(smb + (uint32_t)(j & 1) * 32768u, g_A16 + (size_t)(j + 2) * 64 * HH, tid);
            cp_commit();
        }
        #pragma unroll
        for (int nt = 0; nt < 8; nt++) {
            int col = j * 64 + nt * 8 + (lane & 3) * 2;
            *(uint32_t*)(g_y16 + (size_t)r0 * HH + col) = pack_h(acc[nt][0], acc[nt][1]);
            *(uint32_t*)(g_y16 + (size_t)(r0 + 8) * HH + col) = pack_h(acc[nt][2], acc[nt][3]);
        }
    }
}

// ---------------- kernel 5: fused attention (fp16 single-pass, R11-proven) ----------------
// smem: [0,64K) Y16 staging -> reused as two 32K B buffers | ring @65536: 4x512B.
#define ATF_SMEM (65536 + 2048)
#define RINGF 65536u
__global__ __launch_bounds__(256, 1) void attn_f16(const float* __restrict__ bw,
                                                   float* __restrict__ out) {
    extern __shared__ __align__(1024) char sm[];
    const uint32_t smb = smem_u32(sm);
    const int tid = threadIdx.x, warp = tid >> 5, lane = tid & 31;
    const int b = blockIdx.y, n0 = blockIdx.x * 128;

    const __half* xp = g_x16 + (size_t)b * NN * HH;
    const float* wsrc = g_w + b * NN;
    const float* tsrc = g_t + b * NN;

    stageY16(smb, g_y16 + (size_t)(b * NN + n0) * HH, tid);
    cp_commit();

    uint32_t qrowb = (uint32_t)((warp * 16 + (lane & 15)) * 128 + (lane >> 4) * 16);
    uint32_t sq = qrowb ^ ((qrowb >> 3) & 0x70);
    uint32_t kr0 = (uint32_t)((((lane & 7) + ((lane >> 4) << 3))) * 128 + ((lane & 8) << 1));
    uint32_t sk0 = kr0 ^ ((kr0 >> 3) & 0x70);

    cp_wait<0>(); __syncthreads();
    uint32_t ahr[16][4];
    preloadA(smb, sq, ahr);
    __syncthreads();   // preloads done before the Y area is reused as B buffers

    #pragma unroll
    for (int j0 = 0; j0 < 2; j0++) {
        stage64h(smb + (uint32_t)j0 * 32768u, xp + (size_t)j0 * 64 * HH, tid);
        if (tid < 16) cp16(smb + RINGF + (uint32_t)j0 * 512u + tid * 16u,
                           wsrc + j0 * 64 + tid * 4);
        else if (tid < 32) cp16(smb + RINGF + (uint32_t)j0 * 512u + 256u + (tid - 16) * 16u,
                                tsrc + j0 * 64 + (tid - 16) * 4);
        cp_commit();
    }

    float num0 = 0.f, den0 = 0.f, num1 = 0.f, den1 = 0.f;
    for (int j = 0; j < 32; j++) {
        if (j < 31) { cp_wait<1>(); } else { cp_wait<0>(); }
        __syncthreads();
        float acc[8][4];
        #pragma unroll
        for (int a = 0; a < 8; a++)
            #pragma unroll
            for (int b2 = 0; b2 < 4; b2++) acc[a][b2] = 0.f;
        score64h(smb + (uint32_t)(j & 1) * 32768u, ahr, sk0, acc);
        __syncthreads();
        if (j + 2 < 32) {
            stage64h(smb + (uint32_t)(j & 1) * 32768u, xp + (size_t)(j + 2) * 64 * HH, tid);
            if (tid < 16) cp16(smb + RINGF + (uint32_t)((j + 2) & 3) * 512u + tid * 16u,
                               wsrc + (j + 2) * 64 + tid * 4);
            else if (tid < 32) cp16(smb + RINGF + (uint32_t)((j + 2) & 3) * 512u + 256u +
                                        (tid - 16) * 16u,
                                    tsrc + (j + 2) * 64 + (tid - 16) * 4);
            cp_commit();
        }
        const float* wsp = (const float*)(sm + RINGF + (j & 3) * 512);
        const float* tsp = wsp + 64;
        #pragma unroll
        for (int nt = 0; nt < 8; nt++) {
            float2 wv = *(const float2*)(wsp + nt * 8 + (lane & 3) * 2);
            float2 tv = *(const float2*)(tsp + nt * 8 + (lane & 3) * 2);
            float e;
            e = __expf(acc[nt][0] + tv.x); den0 += e; num0 += e * wv.x;
            e = __expf(acc[nt][1] + tv.y); den0 += e; num0 += e * wv.y;
            e = __expf(acc[nt][2] + tv.x); den1 += e; num1 += e * wv.x;
            e = __expf(acc[nt][3] + tv.y); den1 += e; num1 += e * wv.y;
        }
    }
    #pragma unroll
    for (int o = 1; o <= 2; o <<= 1) {
        num0 += __shfl_xor_sync(0xffffffffu, num0, o);
        den0 += __shfl_xor_sync(0xffffffffu, den0, o);
        num1 += __shfl_xor_sync(0xffffffffu, num1, o);
        den1 += __shfl_xor_sync(0xffffffffu, den1, o);
    }
    if (!(lane & 3)) {
        int r = n0 + warp * 16 + (lane >> 2);
        float bwv = __ldg(bw);
        out[b * NN + r] = num0 / den0 + bwv;
        out[b * NN + r + 8] = num1 / den1 + bwv;
    }
}

// ---------------- launch ----------------
extern "C" void kernel_launch(void* const* d_in, const int* in_sizes, int n_in,
                              void* d_out, int out_size) {
    const float* x  = (const float*)d_in[0];
    const float* Wq = (const float*)d_in[1];
    const float* bq = (const float*)d_in[2];
    const float* Wk = (const float*)d_in[3];
    const float* bk = (const float*)d_in[4];
    const float* Wv = (const float*)d_in[5];
    const float* bv = (const float*)d_in[6];
    const float* Ww = (const float*)d_in[7];
    const float* bw = (const float*)d_in[8];
    float* out = (float*)d_out;
    (void)bk;

    cudaFuncSetAttribute(amat_mma, cudaFuncAttributeMaxDynamicSharedMemorySize, AM_SMEM);
    cudaFuncSetAttribute(y16_mma, cudaFuncAttributeMaxDynamicSharedMemorySize, Y16_SMEM);
    cudaFuncSetAttribute(attn_f16, cudaFuncAttributeMaxDynamicSharedMemorySize, ATF_SMEM);

    prep_kernel<<<1, 256>>>(Wv, Ww, bv, Wk, bq);
    prep_w2_kernel<<<dim3(2, 256), 256>>>(Wq, Wk);
    amat_mma<<<dim3(2, 8), 256, AM_SMEM>>>();        // Amat -> fp16
    xw_kernel<<<BB * NN / 8, 256>>>(x);              // x16, w, t
    y16_mma<<<128, 256, Y16_SMEM>>>();               // y = x * Amat (fp16)
    attn_f16<<<dim3(16, 8), 256, ATF_SMEM>>>(bw, out);
}